// round 1
// baseline (speedup 1.0000x reference)
#include <cuda_runtime.h>
#include <math.h>

// ---------------- scratch (device globals; no allocation) ----------------
#define NPIX 16384              // 128*128
__device__ __align__(16) float g_bufA[4 * 256 * NPIX];    // 64 MB
__device__ __align__(16) float g_bufB[4 * 256 * NPIX];    // 64 MB
__device__ __align__(16) float g_off [4 * 100 * NPIX];    // 26 MB
__device__ __align__(16) float g_wT  [2 * 25 * 128 * 256];// 6.4 MB
__device__ __align__(16) float g_owT [256 * 25 * 100];    // 2.56 MB
__device__ __align__(16) float g_rT  [256 * 128];
__device__ float g_pool[1024];
__device__ float g_scale[1024];

// ---------------- concat ----------------
__global__ void concat_kernel(const float4* __restrict__ a,
                              const float4* __restrict__ b2,
                              float4* __restrict__ dst) {
    int i = blockIdx.x * 256 + threadIdx.x;      // < 4,194,304
    int b = i >> 20;
    int r = i & 0xFFFFF;
    int c = r >> 12;
    int p = r & 4095;
    float4 v = (c < 128) ? a[(((b << 7) + c) << 12) + p]
                         : b2[(((b << 7) + (c - 128)) << 12) + p];
    dst[i] = v;
}

// ---------------- weight transposes ----------------
__global__ void transpose_dcnw(const float* __restrict__ w, float* __restrict__ dst) {
    int idx = blockIdx.x * 256 + threadIdx.x;    // < 1,638,400
    int o = idx & 255;
    int t = idx >> 8;           // (g*25+k)*128 + c
    int c = t & 127;
    int gk = t >> 7;            // 0..49
    int k = gk % 25, g = gk / 25;
    dst[idx] = w[o * 6400 + (g * 128 + c) * 25 + k];
}

__global__ void transpose_offw(const float* __restrict__ w, float* __restrict__ dst) {
    int idx = blockIdx.x * 256 + threadIdx.x;    // < 640,000
    int o = idx % 100;
    int t = idx / 100;
    int tap = t % 25;
    int c = t / 25;
    dst[idx] = w[o * 6400 + c * 25 + tap];
}

__global__ void transpose_redw(const float* __restrict__ w, float* __restrict__ dst) {
    int idx = blockIdx.x * 256 + threadIdx.x;    // < 32768
    int o = idx & 127;
    int c = idx >> 7;
    dst[idx] = w[o * 256 + c];
}

// ---------------- offset conv: 256ch in, 100ch out, 5x5 pad2 ----------------
// block: 256 thr = 16x16 spatial tile; grid (64, B, 4 cout-chunks of 25)
__global__ void __launch_bounds__(256) offconv_kernel(
    const float* __restrict__ xin, const float* __restrict__ offwT,
    const float* __restrict__ offb, float* __restrict__ offout) {
    const int tid = threadIdx.x;
    const int b = blockIdx.y;
    const int obase = blockIdx.z * 25;
    const int ty0 = (blockIdx.x >> 3) << 4;
    const int tx0 = (blockIdx.x & 7) << 4;
    const int ty = tid >> 4, tx = tid & 15;

    __shared__ __align__(16) float xt[4][20][20];
    __shared__ __align__(16) float ws[4][25][28];

    float4 acc[7];
#pragma unroll
    for (int j = 0; j < 7; j++) acc[j] = make_float4(0.f, 0.f, 0.f, 0.f);

    for (int cb = 0; cb < 256; cb += 4) {
        __syncthreads();
        for (int i = tid; i < 1600; i += 256) {
            int c = i / 400;
            int r = (i / 20) % 20;
            int col = i % 20;
            int gy = ty0 + r - 2, gx = tx0 + col - 2;
            float v = 0.f;
            if (gy >= 0 && gy < 128 && gx >= 0 && gx < 128)
                v = xin[((b * 256 + cb + c) * NPIX) + gy * 128 + gx];
            xt[c][r][col] = v;
        }
        for (int i = tid; i < 2800; i += 256) {
            int c = i / 700;
            int r = i % 700;
            int tap = r / 28;
            int o = r % 28;
            float v = 0.f;
            if (o < 25) v = offwT[(cb + c) * 2500 + tap * 100 + obase + o];
            ((float*)ws)[i] = v;
        }
        __syncthreads();
        for (int c = 0; c < 4; c++) {
            for (int kh = 0; kh < 5; kh++) {
#pragma unroll
                for (int kw = 0; kw < 5; kw++) {
                    float v = xt[c][ty + kh][tx + kw];
                    const float4* wp = (const float4*)ws[c][kh * 5 + kw];
#pragma unroll
                    for (int j = 0; j < 7; j++) {
                        float4 w = wp[j];
                        acc[j].x += v * w.x; acc[j].y += v * w.y;
                        acc[j].z += v * w.z; acc[j].w += v * w.w;
                    }
                }
            }
        }
    }
    const int y = ty0 + ty, x = tx0 + tx;
    const float* accf = (const float*)acc;
#pragma unroll
    for (int o = 0; o < 25; o++) {
        float v = accf[o] + offb[obase + o];
        offout[(b * 100 + obase + o) * NPIX + y * 128 + x] = v;
    }
}

// ---------------- deformable conv + BN + ReLU ----------------
// block: 256 thr; 32-pixel horizontal strip; all 256 couts accumulated.
// grid (512 strips, B). warp = fixed ocol x 32 pixels.
__global__ void __launch_bounds__(256) deform_kernel(
    const float* __restrict__ xin, const float* __restrict__ off,
    const float* __restrict__ wT,
    const float* __restrict__ bng, const float* __restrict__ bnb,
    const float* __restrict__ bnm, const float* __restrict__ bnv,
    float* __restrict__ yout) {
    const int tid = threadIdx.x;
    const int b = blockIdx.y;
    const int strip = blockIdx.x;
    const int row = strip >> 2;
    const int x0 = (strip & 3) << 5;

    __shared__ float sPy[32], sPx[32];
    __shared__ float sS[32][9];
    __shared__ __align__(16) float sW[2048];

    const int sp = tid >> 3;   // sample pixel 0..31
    const int sc = tid & 7;    // sample channel 0..7
    const int pix = tid & 31;  // fma pixel
    const int ocol = tid >> 5; // fma cout group (8 groups of 32)

    float4 acc[8];
#pragma unroll
    for (int j = 0; j < 8; j++) acc[j] = make_float4(0.f, 0.f, 0.f, 0.f);

    for (int g = 0; g < 2; g++) {
        const float* xg = xin + (b * 256 + g * 128) * NPIX;
        for (int k = 0; k < 25; k++) {
            const int kh = k / 5, kw = k % 5;
            __syncthreads();
            if (tid < 32) {
                const int ch = b * 100 + g * 50 + 2 * k;
                float oy = off[ch * NPIX + row * 128 + x0 + tid];
                float ox = off[(ch + 1) * NPIX + row * 128 + x0 + tid];
                sPy[tid] = (float)(row + kh - 2) + oy;
                sPx[tid] = (float)(x0 + tid + kw - 2) + ox;
            }
            __syncthreads();
            const float py = sPy[sp], px = sPx[sp];
            const float y0f = floorf(py), x0f = floorf(px);
            const float wy1 = py - y0f, wx1 = px - x0f;
            const float wy0 = 1.f - wy1, wx0 = 1.f - wx1;
            const int iy0 = (int)y0f, ix0 = (int)x0f;
            const bool vy0 = (iy0 >= 0) && (iy0 < 128);
            const bool vy1 = (iy0 >= -1) && (iy0 < 127);
            const bool vx0 = (ix0 >= 0) && (ix0 < 128);
            const bool vx1 = (ix0 >= -1) && (ix0 < 127);
            const int base00 = iy0 * 128 + ix0;
            const float* wgk = wT + (g * 25 + k) * 128 * 256;

            for (int cc = 0; cc < 16; cc++) {
                const float* plane = xg + (cc * 8 + sc) * NPIX;
                float v00 = (vy0 && vx0) ? plane[base00] : 0.f;
                float v01 = (vy0 && vx1) ? plane[base00 + 1] : 0.f;
                float v10 = (vy1 && vx0) ? plane[base00 + 128] : 0.f;
                float v11 = (vy1 && vx1) ? plane[base00 + 129] : 0.f;
                float sval = wy0 * (wx0 * v00 + wx1 * v01)
                           + wy1 * (wx0 * v10 + wx1 * v11);
                const float4* wsrc = (const float4*)(wgk + cc * 2048);
                float4 w0 = wsrc[tid];
                float4 w1 = wsrc[tid + 256];
                __syncthreads();   // previous chunk's FMA done reading sS/sW
                sS[sp][sc] = sval;
                ((float4*)sW)[tid] = w0;
                ((float4*)sW)[tid + 256] = w1;
                __syncthreads();
#pragma unroll
                for (int c = 0; c < 8; c++) {
                    const float s = sS[pix][c];
                    const float4* w4 = (const float4*)&sW[c * 256 + ocol * 32];
#pragma unroll
                    for (int j = 0; j < 8; j++) {
                        float4 w = w4[j];
                        acc[j].x += s * w.x; acc[j].y += s * w.y;
                        acc[j].z += s * w.z; acc[j].w += s * w.w;
                    }
                }
            }
        }
    }
    // epilogue: BN + ReLU, coalesced (warp writes 32 consecutive pixels per o)
    const int pbase = row * 128 + x0 + pix;
    const float* accf = (const float*)acc;
#pragma unroll
    for (int j = 0; j < 32; j++) {
        int o = ocol * 32 + j;
        float inv = bng[o] * rsqrtf(bnv[o] + 1e-5f);
        float beta = bnb[o] - bnm[o] * inv;
        float v = accf[j] * inv + beta;
        yout[(b * 256 + o) * NPIX + pbase] = fmaxf(v, 0.f);
    }
}

// ---------------- SE: pool / mlp / scale ----------------
__global__ void pool_kernel(const float* __restrict__ y, float* __restrict__ pool) {
    int bc = blockIdx.x;  // 0..1023
    const float* plane = y + bc * NPIX;
    float s = 0.f;
    for (int i = threadIdx.x; i < NPIX; i += 256) s += plane[i];
    __shared__ float red[256];
    red[threadIdx.x] = s;
    __syncthreads();
    for (int st = 128; st > 0; st >>= 1) {
        if (threadIdx.x < st) red[threadIdx.x] += red[threadIdx.x + st];
        __syncthreads();
    }
    if (threadIdx.x == 0) pool[bc] = red[0] * (1.f / NPIX);
}

__global__ void se_kernel(const float* __restrict__ pool,
                          const float* __restrict__ w1,
                          const float* __restrict__ w2,
                          float* __restrict__ scale) {
    int b = blockIdx.x;
    int tid = threadIdx.x;
    __shared__ float sp[256], sh[16];
    sp[tid] = pool[b * 256 + tid];
    __syncthreads();
    if (tid < 16) {
        float a = 0.f;
        for (int c = 0; c < 256; c++) a += sp[c] * w1[tid * 256 + c];
        sh[tid] = fmaxf(a, 0.f);
    }
    __syncthreads();
    float a = 0.f;
#pragma unroll
    for (int j = 0; j < 16; j++) a += sh[j] * w2[tid * 16 + j];
    scale[b * 256 + tid] = 1.f / (1.f + expf(-a));
}

__global__ void scale_kernel(float4* __restrict__ y, const float* __restrict__ sc) {
    int i = blockIdx.x * 256 + threadIdx.x;  // < 4,194,304
    float s = sc[i >> 12];
    float4 v = y[i];
    v.x *= s; v.y *= s; v.z *= s; v.w *= s;
    y[i] = v;
}

// ---------------- final 1x1 conv + BN + ReLU ----------------
// block 256 thr: 64 pixels x 128 couts; grid (256, B)
__global__ void __launch_bounds__(256) final_kernel(
    const float* __restrict__ xin, const float* __restrict__ redT,
    const float* __restrict__ bng, const float* __restrict__ bnb,
    const float* __restrict__ bnm, const float* __restrict__ bnv,
    float* __restrict__ out) {
    const int tid = threadIdx.x;
    const int b = blockIdx.y;
    const int p0 = blockIdx.x * 64;
    const int px = tid & 63, og = tid >> 6;
    __shared__ __align__(16) float sX[8][64];
    __shared__ __align__(16) float sWf[8][128];
    float4 acc[8];
#pragma unroll
    for (int j = 0; j < 8; j++) acc[j] = make_float4(0.f, 0.f, 0.f, 0.f);

    for (int cb = 0; cb < 256; cb += 8) {
        __syncthreads();
        {
            int i = tid;
            sX[i >> 6][i & 63] = xin[(b * 256 + cb + (i >> 6)) * NPIX + p0 + (i & 63)];
            i = tid + 256;
            sX[i >> 6][i & 63] = xin[(b * 256 + cb + (i >> 6)) * NPIX + p0 + (i & 63)];
            for (int t = tid; t < 1024; t += 256)
                sWf[t >> 7][t & 127] = redT[(cb + (t >> 7)) * 128 + (t & 127)];
        }
        __syncthreads();
#pragma unroll
        for (int c = 0; c < 8; c++) {
            float xv = sX[c][px];
            const float4* w4 = (const float4*)&sWf[c][og * 32];
#pragma unroll
            for (int j = 0; j < 8; j++) {
                float4 w = w4[j];
                acc[j].x += xv * w.x; acc[j].y += xv * w.y;
                acc[j].z += xv * w.z; acc[j].w += xv * w.w;
            }
        }
    }
    const float* accf = (const float*)acc;
#pragma unroll
    for (int j = 0; j < 32; j++) {
        int o = og * 32 + j;
        float inv = bng[o] * rsqrtf(bnv[o] + 1e-5f);
        float beta = bnb[o] - bnm[o] * inv;
        float v = accf[j] * inv + beta;
        out[(b * 128 + o) * NPIX + p0 + px] = fmaxf(v, 0.f);
    }
}

// ---------------- launch ----------------
extern "C" void kernel_launch(void* const* d_in, const int* in_sizes, int n_in,
                              void* d_out, int out_size) {
    const float* bev1   = (const float*)d_in[0];
    const float* bev2   = (const float*)d_in[1];
    const float* off_w1 = (const float*)d_in[2];
    const float* off_b1 = (const float*)d_in[3];
    const float* dcn_w1 = (const float*)d_in[4];
    const float* bn1_g  = (const float*)d_in[5];
    const float* bn1_b  = (const float*)d_in[6];
    const float* bn1_m  = (const float*)d_in[7];
    const float* bn1_v  = (const float*)d_in[8];
    const float* se1_w1 = (const float*)d_in[9];
    const float* se1_w2 = (const float*)d_in[10];
    const float* off_w2 = (const float*)d_in[11];
    const float* off_b2 = (const float*)d_in[12];
    const float* dcn_w2 = (const float*)d_in[13];
    const float* bn2_g  = (const float*)d_in[14];
    const float* bn2_b  = (const float*)d_in[15];
    const float* bn2_m  = (const float*)d_in[16];
    const float* bn2_v  = (const float*)d_in[17];
    const float* se2_w1 = (const float*)d_in[18];
    const float* se2_w2 = (const float*)d_in[19];
    const float* red_w  = (const float*)d_in[20];
    const float* bn3_g  = (const float*)d_in[21];
    const float* bn3_b  = (const float*)d_in[22];
    const float* bn3_m  = (const float*)d_in[23];
    const float* bn3_v  = (const float*)d_in[24];

    float *A, *B, *OFF, *WT, *OWT, *RT, *POOL, *SCALE;
    cudaGetSymbolAddress((void**)&A,    g_bufA);
    cudaGetSymbolAddress((void**)&B,    g_bufB);
    cudaGetSymbolAddress((void**)&OFF,  g_off);
    cudaGetSymbolAddress((void**)&WT,   g_wT);
    cudaGetSymbolAddress((void**)&OWT,  g_owT);
    cudaGetSymbolAddress((void**)&RT,   g_rT);
    cudaGetSymbolAddress((void**)&POOL, g_pool);
    cudaGetSymbolAddress((void**)&SCALE,g_scale);

    concat_kernel<<<16384, 256>>>((const float4*)bev1, (const float4*)bev2, (float4*)A);

    // ---- stage 1 ----
    transpose_dcnw<<<6400, 256>>>(dcn_w1, WT);
    transpose_offw<<<2500, 256>>>(off_w1, OWT);
    offconv_kernel<<<dim3(64, 4, 4), 256>>>(A, OWT, off_b1, OFF);
    deform_kernel<<<dim3(512, 4), 256>>>(A, OFF, WT, bn1_g, bn1_b, bn1_m, bn1_v, B);
    pool_kernel<<<1024, 256>>>(B, POOL);
    se_kernel<<<4, 256>>>(POOL, se1_w1, se1_w2, SCALE);
    scale_kernel<<<16384, 256>>>((float4*)B, SCALE);

    // ---- stage 2 ----
    transpose_dcnw<<<6400, 256>>>(dcn_w2, WT);
    transpose_offw<<<2500, 256>>>(off_w2, OWT);
    offconv_kernel<<<dim3(64, 4, 4), 256>>>(B, OWT, off_b2, OFF);
    deform_kernel<<<dim3(512, 4), 256>>>(B, OFF, WT, bn2_g, bn2_b, bn2_m, bn2_v, A);
    pool_kernel<<<1024, 256>>>(A, POOL);
    se_kernel<<<4, 256>>>(POOL, se2_w1, se2_w2, SCALE);
    scale_kernel<<<16384, 256>>>((float4*)A, SCALE);

    // ---- final ----
    transpose_redw<<<128, 256>>>(red_w, RT);
    final_kernel<<<dim3(256, 4), 256>>>(A, RT, bn3_g, bn3_b, bn3_m, bn3_v, (float*)d_out);
}

// round 2
// speedup vs baseline: 1.0384x; 1.0384x over previous
#include <cuda_runtime.h>
#include <math.h>

// ---------------- scratch (device globals; no allocation) ----------------
#define NPIX 16384              // 128*128
__device__ __align__(16) float g_bufA[4 * 256 * NPIX];    // 64 MB NCHW
__device__ __align__(16) float g_bufB[4 * 256 * NPIX];    // 64 MB NCHW
__device__ __align__(16) float g_bufC[4 * 256 * NPIX];    // 64 MB NHWC
__device__ __align__(16) float g_off [4 * 100 * NPIX];    // 26 MB
__device__ __align__(16) float g_wT  [2 * 25 * 128 * 256];// 6.4 MB
__device__ __align__(16) float g_owT [256 * 25 * 100];    // 2.56 MB
__device__ __align__(16) float g_rT  [256 * 128];
__device__ float g_pool[1024];
__device__ float g_scale[1024];

// ---------------- concat ----------------
__global__ void concat_kernel(const float4* __restrict__ a,
                              const float4* __restrict__ b2,
                              float4* __restrict__ dst) {
    int i = blockIdx.x * 256 + threadIdx.x;      // < 4,194,304
    int b = i >> 20;
    int r = i & 0xFFFFF;
    int c = r >> 12;
    int p = r & 4095;
    float4 v = (c < 128) ? a[(((b << 7) + c) << 12) + p]
                         : b2[(((b << 7) + (c - 128)) << 12) + p];
    dst[i] = v;
}

// ---------------- NCHW -> NHWC transpose (32x32 tiles) ----------------
__global__ void __launch_bounds__(256) to_nhwc(const float* __restrict__ in,
                                               float* __restrict__ outp) {
    __shared__ float tile[32][33];
    const int bp = blockIdx.x;   // 0..511 pixel tiles
    const int bc = blockIdx.y;   // 0..7 channel tiles
    const int b  = blockIdx.z;
    const int tx = threadIdx.x & 31, ty = threadIdx.x >> 5;
    const float* src = in + ((size_t)b * 256 + bc * 32) * NPIX + bp * 32;
#pragma unroll
    for (int r = 0; r < 4; r++) {
        int c = ty + r * 8;
        tile[c][tx] = src[(size_t)c * NPIX + tx];
    }
    __syncthreads();
    float* dst = outp + ((size_t)b * NPIX + bp * 32) * 256 + bc * 32;
#pragma unroll
    for (int r = 0; r < 4; r++) {
        int p = ty + r * 8;
        dst[(size_t)p * 256 + tx] = tile[tx][p];
    }
}

// ---------------- weight transposes ----------------
__global__ void transpose_dcnw(const float* __restrict__ w, float* __restrict__ dst) {
    int idx = blockIdx.x * 256 + threadIdx.x;    // < 1,638,400
    int o = idx & 255;
    int t = idx >> 8;           // (g*25+k)*128 + c
    int c = t & 127;
    int gk = t >> 7;            // 0..49
    int k = gk % 25, g = gk / 25;
    dst[idx] = w[o * 6400 + (g * 128 + c) * 25 + k];
}

__global__ void transpose_offw(const float* __restrict__ w, float* __restrict__ dst) {
    int idx = blockIdx.x * 256 + threadIdx.x;    // < 640,000
    int o = idx % 100;
    int t = idx / 100;
    int tap = t % 25;
    int c = t / 25;
    dst[idx] = w[o * 6400 + c * 25 + tap];
}

__global__ void transpose_redw(const float* __restrict__ w, float* __restrict__ dst) {
    int idx = blockIdx.x * 256 + threadIdx.x;    // < 32768
    int o = idx & 127;
    int c = idx >> 7;
    dst[idx] = w[o * 256 + c];
}

// ---------------- offset conv: 256ch in, 100ch out, 5x5 pad2 ----------------
// block: 256 thr = 16x16 spatial tile; grid (64, B, 4 cout-chunks of 25)
__global__ void __launch_bounds__(256) offconv_kernel(
    const float* __restrict__ xin, const float* __restrict__ offwT,
    const float* __restrict__ offb, float* __restrict__ offout) {
    const int tid = threadIdx.x;
    const int b = blockIdx.y;
    const int obase = blockIdx.z * 25;
    const int ty0 = (blockIdx.x >> 3) << 4;
    const int tx0 = (blockIdx.x & 7) << 4;
    const int ty = tid >> 4, tx = tid & 15;

    __shared__ __align__(16) float xt[8][20][20];
    __shared__ __align__(16) float ws[8][25][28];

    float4 acc[7];
#pragma unroll
    for (int j = 0; j < 7; j++) acc[j] = make_float4(0.f, 0.f, 0.f, 0.f);

    for (int cb = 0; cb < 256; cb += 8) {
        __syncthreads();
        for (int i = tid; i < 3200; i += 256) {
            int c = i / 400;
            int r = (i / 20) % 20;
            int col = i % 20;
            int gy = ty0 + r - 2, gx = tx0 + col - 2;
            float v = 0.f;
            if (gy >= 0 && gy < 128 && gx >= 0 && gx < 128)
                v = xin[((b * 256 + cb + c) * NPIX) + gy * 128 + gx];
            xt[c][r][col] = v;
        }
        for (int i = tid; i < 5600; i += 256) {
            int c = i / 700;
            int r = i % 700;
            int tap = r / 28;
            int o = r % 28;
            float v = 0.f;
            if (o < 25) v = offwT[(cb + c) * 2500 + tap * 100 + obase + o];
            ((float*)ws)[i] = v;
        }
        __syncthreads();
        for (int c = 0; c < 8; c++) {
            for (int kh = 0; kh < 5; kh++) {
#pragma unroll
                for (int kw = 0; kw < 5; kw++) {
                    float v = xt[c][ty + kh][tx + kw];
                    const float4* wp = (const float4*)ws[c][kh * 5 + kw];
#pragma unroll
                    for (int j = 0; j < 7; j++) {
                        float4 w = wp[j];
                        acc[j].x += v * w.x; acc[j].y += v * w.y;
                        acc[j].z += v * w.z; acc[j].w += v * w.w;
                    }
                }
            }
        }
    }
    const int y = ty0 + ty, x = tx0 + tx;
    const float* accf = (const float*)acc;
#pragma unroll
    for (int o = 0; o < 25; o++) {
        float v = accf[o] + offb[obase + o];
        offout[(b * 100 + obase + o) * NPIX + y * 128 + x] = v;
    }
}

// ---------------- deformable conv v2 (NHWC sampling) + BN + ReLU ----------------
// block: 512 thr; tile = 1 full row (128 px) x 256 couts; grid (128 rows, B).
// warp = (pxblk 0..3, oblk 0..3); lane px = pxblk*32+lane, outs = oblk*64..+63.
__global__ void __launch_bounds__(512, 1) deform2_kernel(
    const float* __restrict__ xh,    // NHWC [b][p][256]
    const float* __restrict__ off,   // NCHW [b][100][p]
    const float* __restrict__ wT,    // [50][128][256]
    const float* __restrict__ bng, const float* __restrict__ bnb,
    const float* __restrict__ bnm, const float* __restrict__ bnv,
    float* __restrict__ yout) {
    extern __shared__ float sm[];
    float*  sPy = sm;                       // 128
    float*  sPx = sm + 128;                 // 128
    float*  sS  = sm + 256;                 // 128c x 132 (padded px)
    float4* sW  = (float4*)(sm + 256 + 128 * 132); // 2 x 512 float4 (8c x 256o)

    const int tid = threadIdx.x;
    const int b = blockIdx.y;
    const int row = blockIdx.x;
    const int lane = tid & 31, warp = tid >> 5;
    const int pxblk = warp >> 2, oblk = warp & 3;
    const int mypx = pxblk * 32 + lane;
    const int sp = tid >> 2, cq = tid & 3;   // sampler: pixel / channel-quarter

    float4 acc[16];
#pragma unroll
    for (int j = 0; j < 16; j++) acc[j] = make_float4(0.f, 0.f, 0.f, 0.f);

    const float4 zero4 = make_float4(0.f, 0.f, 0.f, 0.f);

    for (int g = 0; g < 2; g++) {
        const float* xgb = xh + (size_t)b * NPIX * 256 + g * 128 + cq * 32;
        for (int k = 0; k < 25; k++) {
            const int kh = k / 5, kw = k % 5;
            __syncthreads();    // prior tap finished reading sS / coords
            if (tid < 128) {
                const int ch = b * 100 + g * 50 + 2 * k;
                float oy = off[(size_t)ch * NPIX + row * 128 + tid];
                float ox = off[(size_t)(ch + 1) * NPIX + row * 128 + tid];
                sPy[tid] = (float)(row + kh - 2) + oy;
                sPx[tid] = (float)(tid + kw - 2) + ox;
            }
            __syncthreads();

            // ---- sample 128 px x 128 ch into sS (each thread: 1 px, 32 ch) ----
            const float py = sPy[sp], px = sPx[sp];
            const float y0f = floorf(py), x0f = floorf(px);
            const float wy1 = py - y0f, wx1 = px - x0f;
            const float wy0 = 1.f - wy1, wx0 = 1.f - wx1;
            const int iy = (int)y0f, ix = (int)x0f;
            const bool vy0 = (iy >= 0) & (iy < 128);
            const bool vy1 = (iy >= -1) & (iy < 127);
            const bool vx0 = (ix >= 0) & (ix < 128);
            const bool vx1 = (ix >= -1) & (ix < 127);
            const bool p00 = vy0 & vx0, p01 = vy0 & vx1;
            const bool p10 = vy1 & vx0, p11 = vy1 & vx1;
            const long base = ((long)iy * 128 + ix) * 256;
            const float4* q00 = (const float4*)(xgb + base);
            const float4* q01 = (const float4*)(xgb + base + 256);
            const float4* q10 = (const float4*)(xgb + base + 128 * 256);
            const float4* q11 = (const float4*)(xgb + base + 128 * 256 + 256);
#pragma unroll
            for (int j = 0; j < 8; j++) {
                float4 a = p00 ? q00[j] : zero4;
                float4 bb = p01 ? q01[j] : zero4;
                float4 c = p10 ? q10[j] : zero4;
                float4 d = p11 ? q11[j] : zero4;
                const int c0 = cq * 32 + j * 4;
                sS[(c0 + 0) * 132 + sp] = wy0 * (wx0 * a.x + wx1 * bb.x) + wy1 * (wx0 * c.x + wx1 * d.x);
                sS[(c0 + 1) * 132 + sp] = wy0 * (wx0 * a.y + wx1 * bb.y) + wy1 * (wx0 * c.y + wx1 * d.y);
                sS[(c0 + 2) * 132 + sp] = wy0 * (wx0 * a.z + wx1 * bb.z) + wy1 * (wx0 * c.z + wx1 * d.z);
                sS[(c0 + 3) * 132 + sp] = wy0 * (wx0 * a.w + wx1 * bb.w) + wy1 * (wx0 * c.w + wx1 * d.w);
            }
            __syncthreads();

            // ---- FMA: out[128px][256o] += S[128px][128c] * W[128c][256o] ----
            const float4* wsrc = (const float4*)(wT + (size_t)(g * 25 + k) * 128 * 256);
            float4 wreg = wsrc[tid];            // chunk 0 prefetch
            for (int cc = 0; cc < 16; cc++) {
                sW[(cc & 1) * 512 + tid] = wreg;
                if (cc < 15) wreg = wsrc[(cc + 1) * 512 + tid];
                __syncthreads();
                const float4* wbuf = &sW[(cc & 1) * 512 + oblk * 16];
                const float* sSc = &sS[(cc * 8) * 132 + mypx];
#pragma unroll
                for (int c = 0; c < 8; c++) {
                    const float s = sSc[c * 132];
                    const float4* wrow = wbuf + c * 64;
#pragma unroll
                    for (int j = 0; j < 16; j++) {
                        float4 w = wrow[j];
                        acc[j].x += s * w.x; acc[j].y += s * w.y;
                        acc[j].z += s * w.z; acc[j].w += s * w.w;
                    }
                }
                // no second barrier: ping-pong buffer is 2 iterations deep
            }
        }
    }

    // epilogue: BN + ReLU, coalesced over px
    const int pbase = row * 128 + mypx;
    const float* accf = (const float*)acc;
#pragma unroll
    for (int j = 0; j < 64; j++) {
        const int o = oblk * 64 + j;
        float inv = bng[o] * rsqrtf(bnv[o] + 1e-5f);
        float beta = bnb[o] - bnm[o] * inv;
        float v = accf[j] * inv + beta;
        yout[(size_t)(b * 256 + o) * NPIX + pbase] = fmaxf(v, 0.f);
    }
}

// ---------------- SE: pool / mlp / scale ----------------
__global__ void pool_kernel(const float* __restrict__ y, float* __restrict__ pool) {
    int bc = blockIdx.x;  // 0..1023
    const float* plane = y + (size_t)bc * NPIX;
    float s = 0.f;
    for (int i = threadIdx.x; i < NPIX; i += 256) s += plane[i];
    __shared__ float red[256];
    red[threadIdx.x] = s;
    __syncthreads();
    for (int st = 128; st > 0; st >>= 1) {
        if (threadIdx.x < st) red[threadIdx.x] += red[threadIdx.x + st];
        __syncthreads();
    }
    if (threadIdx.x == 0) pool[bc] = red[0] * (1.f / NPIX);
}

__global__ void se_kernel(const float* __restrict__ pool,
                          const float* __restrict__ w1,
                          const float* __restrict__ w2,
                          float* __restrict__ scale) {
    int b = blockIdx.x;
    int tid = threadIdx.x;
    __shared__ float sp[256], sh[16];
    sp[tid] = pool[b * 256 + tid];
    __syncthreads();
    if (tid < 16) {
        float a = 0.f;
        for (int c = 0; c < 256; c++) a += sp[c] * w1[tid * 256 + c];
        sh[tid] = fmaxf(a, 0.f);
    }
    __syncthreads();
    float a = 0.f;
#pragma unroll
    for (int j = 0; j < 16; j++) a += sh[j] * w2[tid * 16 + j];
    scale[b * 256 + tid] = 1.f / (1.f + expf(-a));
}

__global__ void scale_kernel(float4* __restrict__ y, const float* __restrict__ sc) {
    int i = blockIdx.x * 256 + threadIdx.x;  // < 4,194,304
    float s = sc[i >> 12];
    float4 v = y[i];
    v.x *= s; v.y *= s; v.z *= s; v.w *= s;
    y[i] = v;
}

// ---------------- final 1x1 conv + BN + ReLU ----------------
__global__ void __launch_bounds__(256) final_kernel(
    const float* __restrict__ xin, const float* __restrict__ redT,
    const float* __restrict__ bng, const float* __restrict__ bnb,
    const float* __restrict__ bnm, const float* __restrict__ bnv,
    float* __restrict__ out) {
    const int tid = threadIdx.x;
    const int b = blockIdx.y;
    const int p0 = blockIdx.x * 64;
    const int px = tid & 63, og = tid >> 6;
    __shared__ __align__(16) float sX[8][64];
    __shared__ __align__(16) float sWf[8][128];
    float4 acc[8];
#pragma unroll
    for (int j = 0; j < 8; j++) acc[j] = make_float4(0.f, 0.f, 0.f, 0.f);

    for (int cb = 0; cb < 256; cb += 8) {
        __syncthreads();
        {
            int i = tid;
            sX[i >> 6][i & 63] = xin[((size_t)(b * 256 + cb + (i >> 6))) * NPIX + p0 + (i & 63)];
            i = tid + 256;
            sX[i >> 6][i & 63] = xin[((size_t)(b * 256 + cb + (i >> 6))) * NPIX + p0 + (i & 63)];
            for (int t = tid; t < 1024; t += 256)
                sWf[t >> 7][t & 127] = redT[(cb + (t >> 7)) * 128 + (t & 127)];
        }
        __syncthreads();
#pragma unroll
        for (int c = 0; c < 8; c++) {
            float xv = sX[c][px];
            const float4* w4 = (const float4*)&sWf[c][og * 32];
#pragma unroll
            for (int j = 0; j < 8; j++) {
                float4 w = w4[j];
                acc[j].x += xv * w.x; acc[j].y += xv * w.y;
                acc[j].z += xv * w.z; acc[j].w += xv * w.w;
            }
        }
    }
    const float* accf = (const float*)acc;
#pragma unroll
    for (int j = 0; j < 32; j++) {
        int o = og * 32 + j;
        float inv = bng[o] * rsqrtf(bnv[o] + 1e-5f);
        float beta = bnb[o] - bnm[o] * inv;
        float v = accf[j] * inv + beta;
        out[((size_t)(b * 128 + o)) * NPIX + p0 + px] = fmaxf(v, 0.f);
    }
}

// ---------------- launch ----------------
extern "C" void kernel_launch(void* const* d_in, const int* in_sizes, int n_in,
                              void* d_out, int out_size) {
    const float* bev1   = (const float*)d_in[0];
    const float* bev2   = (const float*)d_in[1];
    const float* off_w1 = (const float*)d_in[2];
    const float* off_b1 = (const float*)d_in[3];
    const float* dcn_w1 = (const float*)d_in[4];
    const float* bn1_g  = (const float*)d_in[5];
    const float* bn1_b  = (const float*)d_in[6];
    const float* bn1_m  = (const float*)d_in[7];
    const float* bn1_v  = (const float*)d_in[8];
    const float* se1_w1 = (const float*)d_in[9];
    const float* se1_w2 = (const float*)d_in[10];
    const float* off_w2 = (const float*)d_in[11];
    const float* off_b2 = (const float*)d_in[12];
    const float* dcn_w2 = (const float*)d_in[13];
    const float* bn2_g  = (const float*)d_in[14];
    const float* bn2_b  = (const float*)d_in[15];
    const float* bn2_m  = (const float*)d_in[16];
    const float* bn2_v  = (const float*)d_in[17];
    const float* se2_w1 = (const float*)d_in[18];
    const float* se2_w2 = (const float*)d_in[19];
    const float* red_w  = (const float*)d_in[20];
    const float* bn3_g  = (const float*)d_in[21];
    const float* bn3_b  = (const float*)d_in[22];
    const float* bn3_m  = (const float*)d_in[23];
    const float* bn3_v  = (const float*)d_in[24];

    float *A, *B, *C, *OFF, *WT, *OWT, *RT, *POOL, *SCALE;
    cudaGetSymbolAddress((void**)&A,    g_bufA);
    cudaGetSymbolAddress((void**)&B,    g_bufB);
    cudaGetSymbolAddress((void**)&C,    g_bufC);
    cudaGetSymbolAddress((void**)&OFF,  g_off);
    cudaGetSymbolAddress((void**)&WT,   g_wT);
    cudaGetSymbolAddress((void**)&OWT,  g_owT);
    cudaGetSymbolAddress((void**)&RT,   g_rT);
    cudaGetSymbolAddress((void**)&POOL, g_pool);
    cudaGetSymbolAddress((void**)&SCALE,g_scale);

    const int DEF_SMEM = (256 + 128 * 132 + 2 * 512 * 4) * 4;  // 84992 B
    cudaFuncSetAttribute(deform2_kernel,
                         cudaFuncAttributeMaxDynamicSharedMemorySize, DEF_SMEM);

    concat_kernel<<<16384, 256>>>((const float4*)bev1, (const float4*)bev2, (float4*)A);

    // ---- stage 1 ----
    to_nhwc<<<dim3(512, 8, 4), 256>>>(A, C);
    transpose_dcnw<<<6400, 256>>>(dcn_w1, WT);
    transpose_offw<<<2500, 256>>>(off_w1, OWT);
    offconv_kernel<<<dim3(64, 4, 4), 256>>>(A, OWT, off_b1, OFF);
    deform2_kernel<<<dim3(128, 4), 512, DEF_SMEM>>>(C, OFF, WT, bn1_g, bn1_b, bn1_m, bn1_v, B);
    pool_kernel<<<1024, 256>>>(B, POOL);
    se_kernel<<<4, 256>>>(POOL, se1_w1, se1_w2, SCALE);
    scale_kernel<<<16384, 256>>>((float4*)B, SCALE);

    // ---- stage 2 ----
    to_nhwc<<<dim3(512, 8, 4), 256>>>(B, C);
    transpose_dcnw<<<6400, 256>>>(dcn_w2, WT);
    transpose_offw<<<2500, 256>>>(off_w2, OWT);
    offconv_kernel<<<dim3(64, 4, 4), 256>>>(B, OWT, off_b2, OFF);
    deform2_kernel<<<dim3(128, 4), 512, DEF_SMEM>>>(C, OFF, WT, bn2_g, bn2_b, bn2_m, bn2_v, A);
    pool_kernel<<<1024, 256>>>(A, POOL);
    se_kernel<<<4, 256>>>(POOL, se2_w1, se2_w2, SCALE);
    scale_kernel<<<16384, 256>>>((float4*)A, SCALE);

    // ---- final ----
    transpose_redw<<<128, 256>>>(red_w, RT);
    final_kernel<<<dim3(256, 4), 256>>>(A, RT, bn3_g, bn3_b, bn3_m, bn3_v, (float*)d_out);
}

// round 3
// speedup vs baseline: 1.4774x; 1.4228x over previous
#include <cuda_runtime.h>
#include <math.h>

// ---------------- f32x2 packed helpers ----------------
__device__ __forceinline__ unsigned long long pk2(float x, float y) {
    unsigned long long r;
    asm("mov.b64 %0, {%1, %2};" : "=l"(r) : "f"(x), "f"(y));
    return r;
}
__device__ __forceinline__ void fma2(unsigned long long& d,
                                     unsigned long long a, unsigned long long b) {
    asm("fma.rn.f32x2 %0, %1, %2, %0;" : "+l"(d) : "l"(a), "l"(b));
}
union F4 { float4 v; unsigned long long u[2]; };

// ---------------- scratch (device globals; no allocation) ----------------
#define NPIX 16384              // 128*128
__device__ __align__(16) float g_bufA[4 * 256 * NPIX];    // 64 MB NCHW
__device__ __align__(16) float g_bufB[4 * 256 * NPIX];    // 64 MB NCHW
__device__ __align__(16) float g_bufC[4 * 256 * NPIX];    // 64 MB NHWC
__device__ __align__(16) float g_off [4 * 100 * NPIX];    // 26 MB
__device__ __align__(16) float g_wT  [2 * 25 * 128 * 256];// 6.4 MB
__device__ __align__(16) float g_owT [256 * 25 * 100];    // 2.56 MB
__device__ __align__(16) float g_rT  [256 * 128];
__device__ float g_pool[1024];
__device__ float g_scale[1024];

// ---------------- concat ----------------
__global__ void concat_kernel(const float4* __restrict__ a,
                              const float4* __restrict__ b2,
                              float4* __restrict__ dst) {
    int i = blockIdx.x * 256 + threadIdx.x;      // < 4,194,304
    int b = i >> 20;
    int r = i & 0xFFFFF;
    int c = r >> 12;
    int p = r & 4095;
    float4 v = (c < 128) ? a[(((b << 7) + c) << 12) + p]
                         : b2[(((b << 7) + (c - 128)) << 12) + p];
    dst[i] = v;
}

// ---------------- NCHW -> NHWC transpose (32x32 tiles) ----------------
__global__ void __launch_bounds__(256) to_nhwc(const float* __restrict__ in,
                                               float* __restrict__ outp) {
    __shared__ float tile[32][33];
    const int bp = blockIdx.x;   // 0..511 pixel tiles
    const int bc = blockIdx.y;   // 0..7 channel tiles
    const int b  = blockIdx.z;
    const int tx = threadIdx.x & 31, ty = threadIdx.x >> 5;
    const float* src = in + ((size_t)b * 256 + bc * 32) * NPIX + bp * 32;
#pragma unroll
    for (int r = 0; r < 4; r++) {
        int c = ty + r * 8;
        tile[c][tx] = src[(size_t)c * NPIX + tx];
    }
    __syncthreads();
    float* dst = outp + ((size_t)b * NPIX + bp * 32) * 256 + bc * 32;
#pragma unroll
    for (int r = 0; r < 4; r++) {
        int p = ty + r * 8;
        dst[(size_t)p * 256 + tx] = tile[tx][p];
    }
}

// ---------------- weight transposes ----------------
__global__ void transpose_dcnw(const float* __restrict__ w, float* __restrict__ dst) {
    int idx = blockIdx.x * 256 + threadIdx.x;    // < 1,638,400
    int o = idx & 255;
    int t = idx >> 8;           // (g*25+k)*128 + c
    int c = t & 127;
    int gk = t >> 7;            // 0..49
    int k = gk % 25, g = gk / 25;
    dst[idx] = w[o * 6400 + (g * 128 + c) * 25 + k];
}

__global__ void transpose_offw(const float* __restrict__ w, float* __restrict__ dst) {
    int idx = blockIdx.x * 256 + threadIdx.x;    // < 640,000
    int o = idx % 100;
    int t = idx / 100;
    int tap = t % 25;
    int c = t / 25;
    dst[idx] = w[o * 6400 + c * 25 + tap];
}

__global__ void transpose_redw(const float* __restrict__ w, float* __restrict__ dst) {
    int idx = blockIdx.x * 256 + threadIdx.x;    // < 32768
    int o = idx & 127;
    int c = idx >> 7;
    dst[idx] = w[o * 256 + c];
}

// ---------------- offset conv: 256ch in, 100ch out, 5x5 pad2 (f32x2) --------
// block: 256 thr = 16x16 spatial tile; grid (64, B, 4 cout-chunks of 25)
__global__ void __launch_bounds__(256) offconv_kernel(
    const float* __restrict__ xin, const float* __restrict__ offwT,
    const float* __restrict__ offb, float* __restrict__ offout) {
    const int tid = threadIdx.x;
    const int b = blockIdx.y;
    const int obase = blockIdx.z * 25;
    const int ty0 = (blockIdx.x >> 3) << 4;
    const int tx0 = (blockIdx.x & 7) << 4;
    const int ty = tid >> 4, tx = tid & 15;

    __shared__ __align__(16) float xt[8][20][20];
    __shared__ __align__(16) float ws[8][25][28];

    union { unsigned long long u[14]; float f[28]; } acc;
#pragma unroll
    for (int j = 0; j < 14; j++) acc.u[j] = 0ull;

    for (int cb = 0; cb < 256; cb += 8) {
        __syncthreads();
        for (int i = tid; i < 3200; i += 256) {
            int c = i / 400;
            int r = (i / 20) % 20;
            int col = i % 20;
            int gy = ty0 + r - 2, gx = tx0 + col - 2;
            float v = 0.f;
            if (gy >= 0 && gy < 128 && gx >= 0 && gx < 128)
                v = xin[((b * 256 + cb + c) * NPIX) + gy * 128 + gx];
            xt[c][r][col] = v;
        }
        for (int i = tid; i < 5600; i += 256) {
            int c = i / 700;
            int r = i % 700;
            int tap = r / 28;
            int o = r % 28;
            float v = 0.f;
            if (o < 25) v = offwT[(cb + c) * 2500 + tap * 100 + obase + o];
            ((float*)ws)[i] = v;
        }
        __syncthreads();
        for (int c = 0; c < 8; c++) {
            for (int kh = 0; kh < 5; kh++) {
#pragma unroll
                for (int kw = 0; kw < 5; kw++) {
                    float v = xt[c][ty + kh][tx + kw];
                    unsigned long long vd = pk2(v, v);
                    const F4* wp = (const F4*)ws[c][kh * 5 + kw];
#pragma unroll
                    for (int j = 0; j < 7; j++) {
                        F4 w = wp[j];
                        fma2(acc.u[2 * j], vd, w.u[0]);
                        fma2(acc.u[2 * j + 1], vd, w.u[1]);
                    }
                }
            }
        }
    }
    const int y = ty0 + ty, x = tx0 + tx;
#pragma unroll
    for (int o = 0; o < 25; o++) {
        float v = acc.f[o] + offb[obase + o];
        offout[(b * 100 + obase + o) * NPIX + y * 128 + x] = v;
    }
}

// ---------------- deformable conv v3 (NHWC sampling, f32x2) + BN + ReLU -----
// block: 256 thr; tile = 64 px x 256 couts; grid (256 tiles, B); 2 CTAs/SM.
// FMA: warp = o-group of 32 (8 warps), lane = px pair (2*lane, 2*lane+1).
__global__ void __launch_bounds__(256, 2) deform3_kernel(
    const float* __restrict__ xh,    // NHWC [b][p][256]
    const float* __restrict__ off,   // NCHW [b][100][p]
    const float* __restrict__ wT,    // [50][128][256]
    const float* __restrict__ bng, const float* __restrict__ bnb,
    const float* __restrict__ bnm, const float* __restrict__ bnv,
    float* __restrict__ yout) {
    extern __shared__ float sm[];
    float*  sPy = sm;                         // 64
    float*  sPx = sm + 64;                    // 64
    float*  sS  = sm + 128;                   // 128c x 64px
    float4* sW  = (float4*)(sm + 128 + 8192); // 2 x 512 float4 (8c x 256o)

    const int tid = threadIdx.x;
    const int b = blockIdx.y;
    const int row = blockIdx.x >> 1;
    const int px0 = (blockIdx.x & 1) << 6;

    const int lane = tid & 31, warp = tid >> 5;
    const int o0 = warp * 32;        // this warp's 32 couts
    const int p2 = lane * 2;         // px pair base
    const int sp = tid & 63, cq = tid >> 6;   // sampler: pixel / channel-quarter

    union { unsigned long long u[16]; float f[32]; } a0, a1;
#pragma unroll
    for (int q = 0; q < 16; q++) { a0.u[q] = 0ull; a1.u[q] = 0ull; }

    const float4 zero4 = make_float4(0.f, 0.f, 0.f, 0.f);

    for (int g = 0; g < 2; g++) {
        const float* xgb = xh + (size_t)b * NPIX * 256 + g * 128 + cq * 32;
        for (int k = 0; k < 25; k++) {
            const int kh = k / 5, kw = k % 5;
            __syncthreads();    // prior tap finished reading sS / coords
            if (tid < 64) {
                const int ch = b * 100 + g * 50 + 2 * k;
                float oy = off[(size_t)ch * NPIX + row * 128 + px0 + tid];
                float ox = off[(size_t)(ch + 1) * NPIX + row * 128 + px0 + tid];
                sPy[tid] = (float)(row + kh - 2) + oy;
                sPx[tid] = (float)(px0 + tid + kw - 2) + ox;
            }
            __syncthreads();

            // ---- sample 64 px x 128 ch into sS (thread: 1 px, 32 ch) ----
            const float py = sPy[sp], px = sPx[sp];
            const float y0f = floorf(py), x0f = floorf(px);
            const float wy1 = py - y0f, wx1 = px - x0f;
            const float wy0 = 1.f - wy1, wx0 = 1.f - wx1;
            const float w00 = wy0 * wx0, w01 = wy0 * wx1;
            const float w10 = wy1 * wx0, w11 = wy1 * wx1;
            const int iy = (int)y0f, ix = (int)x0f;
            const bool vy0 = (iy >= 0) & (iy < 128);
            const bool vy1 = (iy >= -1) & (iy < 127);
            const bool vx0 = (ix >= 0) & (ix < 128);
            const bool vx1 = (ix >= -1) & (ix < 127);
            const bool p00 = vy0 & vx0, p01 = vy0 & vx1;
            const bool p10 = vy1 & vx0, p11 = vy1 & vx1;
            const long base = ((long)iy * 128 + ix) * 256;
            const float4* q00 = (const float4*)(xgb + base);
            const float4* q01 = (const float4*)(xgb + base + 256);
            const float4* q10 = (const float4*)(xgb + base + 128 * 256);
            const float4* q11 = (const float4*)(xgb + base + 128 * 256 + 256);
#pragma unroll
            for (int j = 0; j < 8; j++) {
                float4 a = p00 ? q00[j] : zero4;
                float4 bb = p01 ? q01[j] : zero4;
                float4 c = p10 ? q10[j] : zero4;
                float4 d = p11 ? q11[j] : zero4;
                const int c0 = cq * 32 + j * 4;
                sS[(c0 + 0) * 64 + sp] = w00 * a.x + w01 * bb.x + w10 * c.x + w11 * d.x;
                sS[(c0 + 1) * 64 + sp] = w00 * a.y + w01 * bb.y + w10 * c.y + w11 * d.y;
                sS[(c0 + 2) * 64 + sp] = w00 * a.z + w01 * bb.z + w10 * c.z + w11 * d.z;
                sS[(c0 + 3) * 64 + sp] = w00 * a.w + w01 * bb.w + w10 * c.w + w11 * d.w;
            }
            __syncthreads();

            // ---- FMA: out[64px][256o] += S[64px][128c] * W[128c][256o] ----
            const float4* wsrc = (const float4*)(wT + (size_t)(g * 25 + k) * 128 * 256);
            float4 wr0 = wsrc[tid];
            float4 wr1 = wsrc[256 + tid];
            for (int cc = 0; cc < 16; cc++) {
                float4* buf = &sW[(cc & 1) * 512];
                buf[tid] = wr0;
                buf[256 + tid] = wr1;
                if (cc < 15) {
                    wr0 = wsrc[(cc + 1) * 512 + tid];
                    wr1 = wsrc[(cc + 1) * 512 + 256 + tid];
                }
                __syncthreads();
                const float* sBase = &sS[cc * 8 * 64 + p2];
#pragma unroll
                for (int c = 0; c < 8; c++) {
                    float2 s2 = *(const float2*)(sBase + c * 64);
                    unsigned long long sd0 = pk2(s2.x, s2.x);
                    unsigned long long sd1 = pk2(s2.y, s2.y);
                    const F4* wrow = (const F4*)((const float*)buf + c * 256 + o0);
#pragma unroll
                    for (int q4 = 0; q4 < 8; q4++) {
                        F4 w = wrow[q4];
                        fma2(a0.u[2 * q4],     sd0, w.u[0]);
                        fma2(a0.u[2 * q4 + 1], sd0, w.u[1]);
                        fma2(a1.u[2 * q4],     sd1, w.u[0]);
                        fma2(a1.u[2 * q4 + 1], sd1, w.u[1]);
                    }
                }
                // ping-pong buffer, no second barrier needed
            }
        }
    }

    // epilogue: BN + ReLU, float2 store per cout (coalesced over px)
    const size_t pbase = (size_t)row * 128 + px0 + p2;
#pragma unroll
    for (int j = 0; j < 32; j++) {
        const int o = o0 + j;
        float inv = bng[o] * rsqrtf(bnv[o] + 1e-5f);
        float beta = bnb[o] - bnm[o] * inv;
        float2 v = make_float2(fmaxf(a0.f[j] * inv + beta, 0.f),
                               fmaxf(a1.f[j] * inv + beta, 0.f));
        *(float2*)&yout[(size_t)(b * 256 + o) * NPIX + pbase] = v;
    }
}

// ---------------- SE: pool / mlp / scale ----------------
__global__ void pool_kernel(const float* __restrict__ y, float* __restrict__ pool) {
    int bc = blockIdx.x;  // 0..1023
    const float* plane = y + (size_t)bc * NPIX;
    float s = 0.f;
    for (int i = threadIdx.x; i < NPIX; i += 256) s += plane[i];
    __shared__ float red[256];
    red[threadIdx.x] = s;
    __syncthreads();
    for (int st = 128; st > 0; st >>= 1) {
        if (threadIdx.x < st) red[threadIdx.x] += red[threadIdx.x + st];
        __syncthreads();
    }
    if (threadIdx.x == 0) pool[bc] = red[0] * (1.f / NPIX);
}

__global__ void se_kernel(const float* __restrict__ pool,
                          const float* __restrict__ w1,
                          const float* __restrict__ w2,
                          float* __restrict__ scale) {
    int b = blockIdx.x;
    int tid = threadIdx.x;
    __shared__ float sp[256], sh[16];
    sp[tid] = pool[b * 256 + tid];
    __syncthreads();
    if (tid < 16) {
        float a = 0.f;
        for (int c = 0; c < 256; c++) a += sp[c] * w1[tid * 256 + c];
        sh[tid] = fmaxf(a, 0.f);
    }
    __syncthreads();
    float a = 0.f;
#pragma unroll
    for (int j = 0; j < 16; j++) a += sh[j] * w2[tid * 16 + j];
    scale[b * 256 + tid] = 1.f / (1.f + expf(-a));
}

__global__ void scale_kernel(float4* __restrict__ y, const float* __restrict__ sc) {
    int i = blockIdx.x * 256 + threadIdx.x;  // < 4,194,304
    float s = sc[i >> 12];
    float4 v = y[i];
    v.x *= s; v.y *= s; v.z *= s; v.w *= s;
    y[i] = v;
}

// ---------------- final 1x1 conv + BN + ReLU (f32x2) ----------------
__global__ void __launch_bounds__(256) final_kernel(
    const float* __restrict__ xin, const float* __restrict__ redT,
    const float* __restrict__ bng, const float* __restrict__ bnb,
    const float* __restrict__ bnm, const float* __restrict__ bnv,
    float* __restrict__ out) {
    const int tid = threadIdx.x;
    const int b = blockIdx.y;
    const int p0 = blockIdx.x * 64;
    const int px = tid & 63, og = tid >> 6;
    __shared__ __align__(16) float sX[8][64];
    __shared__ __align__(16) float sWf[8][128];
    union { unsigned long long u[16]; float f[32]; } acc;
#pragma unroll
    for (int j = 0; j < 16; j++) acc.u[j] = 0ull;

    for (int cb = 0; cb < 256; cb += 8) {
        __syncthreads();
        {
            int i = tid;
            sX[i >> 6][i & 63] = xin[((size_t)(b * 256 + cb + (i >> 6))) * NPIX + p0 + (i & 63)];
            i = tid + 256;
            sX[i >> 6][i & 63] = xin[((size_t)(b * 256 + cb + (i >> 6))) * NPIX + p0 + (i & 63)];
            for (int t = tid; t < 1024; t += 256)
                sWf[t >> 7][t & 127] = redT[(cb + (t >> 7)) * 128 + (t & 127)];
        }
        __syncthreads();
#pragma unroll
        for (int c = 0; c < 8; c++) {
            float xv = sX[c][px];
            unsigned long long xd = pk2(xv, xv);
            const F4* wp = (const F4*)&sWf[c][og * 32];
#pragma unroll
            for (int j = 0; j < 8; j++) {
                F4 w = wp[j];
                fma2(acc.u[2 * j],     xd, w.u[0]);
                fma2(acc.u[2 * j + 1], xd, w.u[1]);
            }
        }
    }
#pragma unroll
    for (int j = 0; j < 32; j++) {
        int o = og * 32 + j;
        float inv = bng[o] * rsqrtf(bnv[o] + 1e-5f);
        float beta = bnb[o] - bnm[o] * inv;
        float v = acc.f[j] * inv + beta;
        out[((size_t)(b * 128 + o)) * NPIX + p0 + px] = fmaxf(v, 0.f);
    }
}

// ---------------- launch ----------------
extern "C" void kernel_launch(void* const* d_in, const int* in_sizes, int n_in,
                              void* d_out, int out_size) {
    const float* bev1   = (const float*)d_in[0];
    const float* bev2   = (const float*)d_in[1];
    const float* off_w1 = (const float*)d_in[2];
    const float* off_b1 = (const float*)d_in[3];
    const float* dcn_w1 = (const float*)d_in[4];
    const float* bn1_g  = (const float*)d_in[5];
    const float* bn1_b  = (const float*)d_in[6];
    const float* bn1_m  = (const float*)d_in[7];
    const float* bn1_v  = (const float*)d_in[8];
    const float* se1_w1 = (const float*)d_in[9];
    const float* se1_w2 = (const float*)d_in[10];
    const float* off_w2 = (const float*)d_in[11];
    const float* off_b2 = (const float*)d_in[12];
    const float* dcn_w2 = (const float*)d_in[13];
    const float* bn2_g  = (const float*)d_in[14];
    const float* bn2_b  = (const float*)d_in[15];
    const float* bn2_m  = (const float*)d_in[16];
    const float* bn2_v  = (const float*)d_in[17];
    const float* se2_w1 = (const float*)d_in[18];
    const float* se2_w2 = (const float*)d_in[19];
    const float* red_w  = (const float*)d_in[20];
    const float* bn3_g  = (const float*)d_in[21];
    const float* bn3_b  = (const float*)d_in[22];
    const float* bn3_m  = (const float*)d_in[23];
    const float* bn3_v  = (const float*)d_in[24];

    float *A, *B, *C, *OFF, *WT, *OWT, *RT, *POOL, *SCALE;
    cudaGetSymbolAddress((void**)&A,    g_bufA);
    cudaGetSymbolAddress((void**)&B,    g_bufB);
    cudaGetSymbolAddress((void**)&C,    g_bufC);
    cudaGetSymbolAddress((void**)&OFF,  g_off);
    cudaGetSymbolAddress((void**)&WT,   g_wT);
    cudaGetSymbolAddress((void**)&OWT,  g_owT);
    cudaGetSymbolAddress((void**)&RT,   g_rT);
    cudaGetSymbolAddress((void**)&POOL, g_pool);
    cudaGetSymbolAddress((void**)&SCALE,g_scale);

    const int DEF_SMEM = (128 + 128 * 64 + 2 * 512 * 4) * 4;  // 49664 B
    cudaFuncSetAttribute(deform3_kernel,
                         cudaFuncAttributeMaxDynamicSharedMemorySize, DEF_SMEM);

    concat_kernel<<<16384, 256>>>((const float4*)bev1, (const float4*)bev2, (float4*)A);

    // ---- stage 1 ----
    to_nhwc<<<dim3(512, 8, 4), 256>>>(A, C);
    transpose_dcnw<<<6400, 256>>>(dcn_w1, WT);
    transpose_offw<<<2500, 256>>>(off_w1, OWT);
    offconv_kernel<<<dim3(64, 4, 4), 256>>>(A, OWT, off_b1, OFF);
    deform3_kernel<<<dim3(256, 4), 256, DEF_SMEM>>>(C, OFF, WT, bn1_g, bn1_b, bn1_m, bn1_v, B);
    pool_kernel<<<1024, 256>>>(B, POOL);
    se_kernel<<<4, 256>>>(POOL, se1_w1, se1_w2, SCALE);
    scale_kernel<<<16384, 256>>>((float4*)B, SCALE);

    // ---- stage 2 ----
    to_nhwc<<<dim3(512, 8, 4), 256>>>(B, C);
    transpose_dcnw<<<6400, 256>>>(dcn_w2, WT);
    transpose_offw<<<2500, 256>>>(off_w2, OWT);
    offconv_kernel<<<dim3(64, 4, 4), 256>>>(B, OWT, off_b2, OFF);
    deform3_kernel<<<dim3(256, 4), 256, DEF_SMEM>>>(C, OFF, WT, bn2_g, bn2_b, bn2_m, bn2_v, A);
    pool_kernel<<<1024, 256>>>(A, POOL);
    se_kernel<<<4, 256>>>(POOL, se2_w1, se2_w2, SCALE);
    scale_kernel<<<16384, 256>>>((float4*)A, SCALE);

    // ---- final ----
    transpose_redw<<<128, 256>>>(red_w, RT);
    final_kernel<<<dim3(256, 4), 256>>>(A, RT, bn3_g, bn3_b, bn3_m, bn3_v, (float*)d_out);
}

// round 4
// speedup vs baseline: 1.7384x; 1.1767x over previous
#include <cuda_runtime.h>
#include <math.h>

// ---------------- f32x2 packed helpers ----------------
__device__ __forceinline__ unsigned long long pk2(float x, float y) {
    unsigned long long r;
    asm("mov.b64 %0, {%1, %2};" : "=l"(r) : "f"(x), "f"(y));
    return r;
}
__device__ __forceinline__ void fma2(unsigned long long& d,
                                     unsigned long long a, unsigned long long b) {
    asm("fma.rn.f32x2 %0, %1, %2, %0;" : "+l"(d) : "l"(a), "l"(b));
}
union F4 { float4 v; unsigned long long u[2]; };

// ---------------- scratch (device globals; no allocation) ----------------
#define NPIX 16384              // 128*128
__device__ __align__(16) float g_bufA[4 * 256 * NPIX];    // 64 MB NCHW
__device__ __align__(16) float g_bufB[4 * 256 * NPIX];    // 64 MB NCHW
__device__ __align__(16) float g_bufC[4 * 256 * NPIX];    // 64 MB NHWC
__device__ __align__(16) float g_off [4 * 100 * NPIX];    // 26 MB
__device__ __align__(16) float g_wT  [2 * 25 * 128 * 256];// 6.4 MB
__device__ __align__(16) float g_owT [256 * 25 * 100];    // 2.56 MB
__device__ __align__(16) float g_rT  [256 * 128];
__device__ float g_pool[1024];
__device__ float g_scale[1024];

// ---------------- concat ----------------
__global__ void concat_kernel(const float4* __restrict__ a,
                              const float4* __restrict__ b2,
                              float4* __restrict__ dst) {
    int i = blockIdx.x * 256 + threadIdx.x;      // < 4,194,304
    int b = i >> 20;
    int r = i & 0xFFFFF;
    int c = r >> 12;
    int p = r & 4095;
    float4 v = (c < 128) ? a[(((b << 7) + c) << 12) + p]
                         : b2[(((b << 7) + (c - 128)) << 12) + p];
    dst[i] = v;
}

// ---------------- NCHW -> NHWC transpose (32x32 tiles) ----------------
__global__ void __launch_bounds__(256) to_nhwc(const float* __restrict__ in,
                                               float* __restrict__ outp) {
    __shared__ float tile[32][33];
    const int bp = blockIdx.x;   // 0..511 pixel tiles
    const int bc = blockIdx.y;   // 0..7 channel tiles
    const int b  = blockIdx.z;
    const int tx = threadIdx.x & 31, ty = threadIdx.x >> 5;
    const float* src = in + ((size_t)b * 256 + bc * 32) * NPIX + bp * 32;
#pragma unroll
    for (int r = 0; r < 4; r++) {
        int c = ty + r * 8;
        tile[c][tx] = src[(size_t)c * NPIX + tx];
    }
    __syncthreads();
    float* dst = outp + ((size_t)b * NPIX + bp * 32) * 256 + bc * 32;
#pragma unroll
    for (int r = 0; r < 4; r++) {
        int p = ty + r * 8;
        dst[(size_t)p * 256 + tx] = tile[tx][p];
    }
}

// ---------------- weight transposes ----------------
__global__ void transpose_dcnw(const float* __restrict__ w, float* __restrict__ dst) {
    int idx = blockIdx.x * 256 + threadIdx.x;    // < 1,638,400
    int o = idx & 255;
    int t = idx >> 8;           // (g*25+k)*128 + c
    int c = t & 127;
    int gk = t >> 7;            // 0..49
    int k = gk % 25, g = gk / 25;
    dst[idx] = w[o * 6400 + (g * 128 + c) * 25 + k];
}

__global__ void transpose_offw(const float* __restrict__ w, float* __restrict__ dst) {
    int idx = blockIdx.x * 256 + threadIdx.x;    // < 640,000
    int o = idx % 100;
    int t = idx / 100;
    int tap = t % 25;
    int c = t / 25;
    dst[idx] = w[o * 6400 + c * 25 + tap];
}

__global__ void transpose_redw(const float* __restrict__ w, float* __restrict__ dst) {
    int idx = blockIdx.x * 256 + threadIdx.x;    // < 32768
    int o = idx & 127;
    int c = idx >> 7;
    dst[idx] = w[o * 256 + c];
}

// ---------------- offset conv: 256ch in, 100ch out, 5x5 pad2 (f32x2) --------
__global__ void __launch_bounds__(256) offconv_kernel(
    const float* __restrict__ xin, const float* __restrict__ offwT,
    const float* __restrict__ offb, float* __restrict__ offout) {
    const int tid = threadIdx.x;
    const int b = blockIdx.y;
    const int obase = blockIdx.z * 25;
    const int ty0 = (blockIdx.x >> 3) << 4;
    const int tx0 = (blockIdx.x & 7) << 4;
    const int ty = tid >> 4, tx = tid & 15;

    __shared__ __align__(16) float xt[8][20][20];
    __shared__ __align__(16) float ws[8][25][28];

    union { unsigned long long u[14]; float f[28]; } acc;
#pragma unroll
    for (int j = 0; j < 14; j++) acc.u[j] = 0ull;

    for (int cb = 0; cb < 256; cb += 8) {
        __syncthreads();
        for (int i = tid; i < 3200; i += 256) {
            int c = i / 400;
            int r = (i / 20) % 20;
            int col = i % 20;
            int gy = ty0 + r - 2, gx = tx0 + col - 2;
            float v = 0.f;
            if (gy >= 0 && gy < 128 && gx >= 0 && gx < 128)
                v = xin[((b * 256 + cb + c) * NPIX) + gy * 128 + gx];
            xt[c][r][col] = v;
        }
        for (int i = tid; i < 5600; i += 256) {
            int c = i / 700;
            int r = i % 700;
            int tap = r / 28;
            int o = r % 28;
            float v = 0.f;
            if (o < 25) v = offwT[(cb + c) * 2500 + tap * 100 + obase + o];
            ((float*)ws)[i] = v;
        }
        __syncthreads();
        for (int c = 0; c < 8; c++) {
            for (int kh = 0; kh < 5; kh++) {
#pragma unroll
                for (int kw = 0; kw < 5; kw++) {
                    float v = xt[c][ty + kh][tx + kw];
                    unsigned long long vd = pk2(v, v);
                    const F4* wp = (const F4*)ws[c][kh * 5 + kw];
#pragma unroll
                    for (int j = 0; j < 7; j++) {
                        F4 w = wp[j];
                        fma2(acc.u[2 * j], vd, w.u[0]);
                        fma2(acc.u[2 * j + 1], vd, w.u[1]);
                    }
                }
            }
        }
    }
    const int y = ty0 + ty, x = tx0 + tx;
#pragma unroll
    for (int o = 0; o < 25; o++) {
        float v = acc.f[o] + offb[obase + o];
        offout[(b * 100 + obase + o) * NPIX + y * 128 + x] = v;
    }
}

// ---------------- deformable conv v4 + BN + ReLU ----------------
// block: 256 thr; tile = 64 px x 256 couts; grid (256 tiles, B); 2 CTAs/SM.
// Coords for all 50 (g,k) precomputed in smem. Sampler: per LDG inst a warp
// covers 4 pixels x one full 128B line (lane = (px-in-4, 16B chunk)).
// FMA: warp = o-group of 32, lane = px pair, f32x2 accumulators.
#define SS_STRIDE 66
__global__ void __launch_bounds__(256, 2) deform4_kernel(
    const float* __restrict__ xh,    // NHWC [b][p][256]
    const float* __restrict__ off,   // NCHW [b][100][p]
    const float* __restrict__ wT,    // [50][128][256]
    const float* __restrict__ bng, const float* __restrict__ bnb,
    const float* __restrict__ bnm, const float* __restrict__ bnv,
    float* __restrict__ yout) {
    extern __shared__ float sm[];
    float* sPy = sm;                          // [50][64]
    float* sPx = sm + 3200;                   // [50][64]
    float* sS  = sm + 6400;                   // [128][66]
    float* sW  = sm + 6400 + 128 * SS_STRIDE; // [2][16*256]

    const int tid = threadIdx.x;
    const int b = blockIdx.y;
    const int row = blockIdx.x >> 1;
    const int px0 = (blockIdx.x & 1) << 6;

    const int lane = tid & 31, warp = tid >> 5;
    const int o0 = warp * 32;        // FMA: this warp's 32 couts
    const int p2 = lane * 2;         // FMA: px pair base

    // sampler mapping: warp covers (px half, channel quarter)
    const int sh = warp & 1;         // px half (0..1) -> px base sh*32
    const int cq = warp >> 1;        // channel quarter (0..3)
    const int lg = lane >> 3;        // pixel within group of 4
    const int lc = lane & 7;         // 16B chunk within 128B line
    const int c0 = cq * 32 + lc * 4; // this lane's 4 channels

    // ---- precompute bilinear coords for all 50 (g,k) ----
    for (int idx = tid; idx < 3200; idx += 256) {
        int gk = idx >> 6, p = idx & 63;
        int g = gk / 25, k = gk % 25;
        int kh = k / 5, kw = k % 5;
        int ch = b * 100 + g * 50 + 2 * k;
        float oy = off[(size_t)ch * NPIX + row * 128 + px0 + p];
        float ox = off[(size_t)(ch + 1) * NPIX + row * 128 + px0 + p];
        sPy[idx] = (float)(row + kh - 2) + oy;
        sPx[idx] = (float)(px0 + p + kw - 2) + ox;
    }

    union { unsigned long long u[16]; float f[32]; } a0, a1;
#pragma unroll
    for (int q = 0; q < 16; q++) { a0.u[q] = 0ull; a1.u[q] = 0ull; }

    const float4 zero4 = make_float4(0.f, 0.f, 0.f, 0.f);

    for (int gk = 0; gk < 50; gk++) {
        const int g = (gk >= 25) ? 1 : 0;
        const float* xgb = xh + (size_t)b * NPIX * 256 + g * 128 + c0;

        __syncthreads();   // sS free for reuse (covers coords at gk=0)

        // ---- sample 64 px x 128 ch into sS ----
#pragma unroll
        for (int j = 0; j < 8; j++) {
            const int p = sh * 32 + j * 4 + lg;          // local px 0..63
            const float py = sPy[gk * 64 + p];
            const float pxf = sPx[gk * 64 + p];
            const float y0f = floorf(py), x0f = floorf(pxf);
            const float wy1 = py - y0f, wx1 = pxf - x0f;
            const float wy0 = 1.f - wy1, wx0 = 1.f - wx1;
            const float w00 = wy0 * wx0, w01 = wy0 * wx1;
            const float w10 = wy1 * wx0, w11 = wy1 * wx1;
            const int iy = (int)y0f, ix = (int)x0f;
            const bool vy0 = (iy >= 0) & (iy < 128);
            const bool vy1 = (iy >= -1) & (iy < 127);
            const bool vx0 = (ix >= 0) & (ix < 128);
            const bool vx1 = (ix >= -1) & (ix < 127);
            const long base = ((long)iy * 128 + ix) * 256;
            float4 va = (vy0 & vx0) ? *(const float4*)(xgb + base) : zero4;
            float4 vb = (vy0 & vx1) ? *(const float4*)(xgb + base + 256) : zero4;
            float4 vc = (vy1 & vx0) ? *(const float4*)(xgb + base + 128 * 256) : zero4;
            float4 vd = (vy1 & vx1) ? *(const float4*)(xgb + base + 128 * 256 + 256) : zero4;
            float* dst = &sS[c0 * SS_STRIDE + p];
            dst[0]             = w00 * va.x + w01 * vb.x + w10 * vc.x + w11 * vd.x;
            dst[SS_STRIDE]     = w00 * va.y + w01 * vb.y + w10 * vc.y + w11 * vd.y;
            dst[2 * SS_STRIDE] = w00 * va.z + w01 * vb.z + w10 * vc.z + w11 * vd.z;
            dst[3 * SS_STRIDE] = w00 * va.w + w01 * vb.w + w10 * vc.w + w11 * vd.w;
        }
        __syncthreads();

        // ---- FMA: out[64px][256o] += S[64px][128c] * W[128c][256o] ----
        const float4* wsrc = (const float4*)(wT + (size_t)gk * 32768);
        float4 wr0 = wsrc[tid];
        float4 wr1 = wsrc[256 + tid];
        float4 wr2 = wsrc[512 + tid];
        float4 wr3 = wsrc[768 + tid];
        for (int cc = 0; cc < 8; cc++) {
            float* buf = sW + (cc & 1) * 4096;
            ((float4*)buf)[tid]       = wr0;
            ((float4*)buf)[256 + tid] = wr1;
            ((float4*)buf)[512 + tid] = wr2;
            ((float4*)buf)[768 + tid] = wr3;
            if (cc < 7) {
                const float4* nxt = wsrc + (cc + 1) * 1024;
                wr0 = nxt[tid];
                wr1 = nxt[256 + tid];
                wr2 = nxt[512 + tid];
                wr3 = nxt[768 + tid];
            }
            __syncthreads();
            const float* sBase = &sS[(cc * 16) * SS_STRIDE + p2];
#pragma unroll
            for (int c = 0; c < 16; c++) {
                float2 s2 = *(const float2*)(sBase + c * SS_STRIDE);
                unsigned long long sd0 = pk2(s2.x, s2.x);
                unsigned long long sd1 = pk2(s2.y, s2.y);
                const F4* wrow = (const F4*)(buf + c * 256 + o0);
#pragma unroll
                for (int q4 = 0; q4 < 8; q4++) {
                    F4 w = wrow[q4];
                    fma2(a0.u[2 * q4],     sd0, w.u[0]);
                    fma2(a0.u[2 * q4 + 1], sd0, w.u[1]);
                    fma2(a1.u[2 * q4],     sd1, w.u[0]);
                    fma2(a1.u[2 * q4 + 1], sd1, w.u[1]);
                }
            }
            // ping-pong buffer: two barriers separate write from prior read
        }
    }

    // epilogue: BN + ReLU, float2 store per cout (coalesced over px)
    const size_t pbase = (size_t)row * 128 + px0 + p2;
#pragma unroll
    for (int j = 0; j < 32; j++) {
        const int o = o0 + j;
        float inv = bng[o] * rsqrtf(bnv[o] + 1e-5f);
        float beta = bnb[o] - bnm[o] * inv;
        float2 v = make_float2(fmaxf(a0.f[j] * inv + beta, 0.f),
                               fmaxf(a1.f[j] * inv + beta, 0.f));
        *(float2*)&yout[(size_t)(b * 256 + o) * NPIX + pbase] = v;
    }
}

// ---------------- SE: pool / mlp / scale ----------------
__global__ void pool_kernel(const float* __restrict__ y, float* __restrict__ pool) {
    int bc = blockIdx.x;  // 0..1023
    const float* plane = y + (size_t)bc * NPIX;
    float s = 0.f;
    for (int i = threadIdx.x; i < NPIX; i += 256) s += plane[i];
    __shared__ float red[256];
    red[threadIdx.x] = s;
    __syncthreads();
    for (int st = 128; st > 0; st >>= 1) {
        if (threadIdx.x < st) red[threadIdx.x] += red[threadIdx.x + st];
        __syncthreads();
    }
    if (threadIdx.x == 0) pool[bc] = red[0] * (1.f / NPIX);
}

__global__ void se_kernel(const float* __restrict__ pool,
                          const float* __restrict__ w1,
                          const float* __restrict__ w2,
                          float* __restrict__ scale) {
    int b = blockIdx.x;
    int tid = threadIdx.x;
    __shared__ float sp[256], sh[16];
    sp[tid] = pool[b * 256 + tid];
    __syncthreads();
    if (tid < 16) {
        float a = 0.f;
        for (int c = 0; c < 256; c++) a += sp[c] * w1[tid * 256 + c];
        sh[tid] = fmaxf(a, 0.f);
    }
    __syncthreads();
    float a = 0.f;
#pragma unroll
    for (int j = 0; j < 16; j++) a += sh[j] * w2[tid * 16 + j];
    scale[b * 256 + tid] = 1.f / (1.f + expf(-a));
}

__global__ void scale_kernel(float4* __restrict__ y, const float* __restrict__ sc) {
    int i = blockIdx.x * 256 + threadIdx.x;  // < 4,194,304
    float s = sc[i >> 12];
    float4 v = y[i];
    v.x *= s; v.y *= s; v.z *= s; v.w *= s;
    y[i] = v;
}

// ---------------- final 1x1 conv + BN + ReLU (f32x2) ----------------
__global__ void __launch_bounds__(256) final_kernel(
    const float* __restrict__ xin, const float* __restrict__ redT,
    const float* __restrict__ bng, const float* __restrict__ bnb,
    const float* __restrict__ bnm, const float* __restrict__ bnv,
    float* __restrict__ out) {
    const int tid = threadIdx.x;
    const int b = blockIdx.y;
    const int p0 = blockIdx.x * 64;
    const int px = tid & 63, og = tid >> 6;
    __shared__ __align__(16) float sX[8][64];
    __shared__ __align__(16) float sWf[8][128];
    union { unsigned long long u[16]; float f[32]; } acc;
#pragma unroll
    for (int j = 0; j < 16; j++) acc.u[j] = 0ull;

    for (int cb = 0; cb < 256; cb += 8) {
        __syncthreads();
        {
            int i = tid;
            sX[i >> 6][i & 63] = xin[((size_t)(b * 256 + cb + (i >> 6))) * NPIX + p0 + (i & 63)];
            i = tid + 256;
            sX[i >> 6][i & 63] = xin[((size_t)(b * 256 + cb + (i >> 6))) * NPIX + p0 + (i & 63)];
            for (int t = tid; t < 1024; t += 256)
                sWf[t >> 7][t & 127] = redT[(cb + (t >> 7)) * 128 + (t & 127)];
        }
        __syncthreads();
#pragma unroll
        for (int c = 0; c < 8; c++) {
            float xv = sX[c][px];
            unsigned long long xd = pk2(xv, xv);
            const F4* wp = (const F4*)&sWf[c][og * 32];
#pragma unroll
            for (int j = 0; j < 8; j++) {
                F4 w = wp[j];
                fma2(acc.u[2 * j],     xd, w.u[0]);
                fma2(acc.u[2 * j + 1], xd, w.u[1]);
            }
        }
    }
#pragma unroll
    for (int j = 0; j < 32; j++) {
        int o = og * 32 + j;
        float inv = bng[o] * rsqrtf(bnv[o] + 1e-5f);
        float beta = bnb[o] - bnm[o] * inv;
        float v = acc.f[j] * inv + beta;
        out[((size_t)(b * 128 + o)) * NPIX + p0 + px] = fmaxf(v, 0.f);
    }
}

// ---------------- launch ----------------
extern "C" void kernel_launch(void* const* d_in, const int* in_sizes, int n_in,
                              void* d_out, int out_size) {
    const float* bev1   = (const float*)d_in[0];
    const float* bev2   = (const float*)d_in[1];
    const float* off_w1 = (const float*)d_in[2];
    const float* off_b1 = (const float*)d_in[3];
    const float* dcn_w1 = (const float*)d_in[4];
    const float* bn1_g  = (const float*)d_in[5];
    const float* bn1_b  = (const float*)d_in[6];
    const float* bn1_m  = (const float*)d_in[7];
    const float* bn1_v  = (const float*)d_in[8];
    const float* se1_w1 = (const float*)d_in[9];
    const float* se1_w2 = (const float*)d_in[10];
    const float* off_w2 = (const float*)d_in[11];
    const float* off_b2 = (const float*)d_in[12];
    const float* dcn_w2 = (const float*)d_in[13];
    const float* bn2_g  = (const float*)d_in[14];
    const float* bn2_b  = (const float*)d_in[15];
    const float* bn2_m  = (const float*)d_in[16];
    const float* bn2_v  = (const float*)d_in[17];
    const float* se2_w1 = (const float*)d_in[18];
    const float* se2_w2 = (const float*)d_in[19];
    const float* red_w  = (const float*)d_in[20];
    const float* bn3_g  = (const float*)d_in[21];
    const float* bn3_b  = (const float*)d_in[22];
    const float* bn3_m  = (const float*)d_in[23];
    const float* bn3_v  = (const float*)d_in[24];

    float *A, *B, *C, *OFF, *WT, *OWT, *RT, *POOL, *SCALE;
    cudaGetSymbolAddress((void**)&A,    g_bufA);
    cudaGetSymbolAddress((void**)&B,    g_bufB);
    cudaGetSymbolAddress((void**)&C,    g_bufC);
    cudaGetSymbolAddress((void**)&OFF,  g_off);
    cudaGetSymbolAddress((void**)&WT,   g_wT);
    cudaGetSymbolAddress((void**)&OWT,  g_owT);
    cudaGetSymbolAddress((void**)&RT,   g_rT);
    cudaGetSymbolAddress((void**)&POOL, g_pool);
    cudaGetSymbolAddress((void**)&SCALE,g_scale);

    const int DEF_SMEM = (3200 + 3200 + 128 * SS_STRIDE + 2 * 4096) * 4;  // 92160 B
    cudaFuncSetAttribute(deform4_kernel,
                         cudaFuncAttributeMaxDynamicSharedMemorySize, DEF_SMEM);

    concat_kernel<<<16384, 256>>>((const float4*)bev1, (const float4*)bev2, (float4*)A);

    // ---- stage 1 ----
    to_nhwc<<<dim3(512, 8, 4), 256>>>(A, C);
    transpose_dcnw<<<6400, 256>>>(dcn_w1, WT);
    transpose_offw<<<2500, 256>>>(off_w1, OWT);
    offconv_kernel<<<dim3(64, 4, 4), 256>>>(A, OWT, off_b1, OFF);
    deform4_kernel<<<dim3(256, 4), 256, DEF_SMEM>>>(C, OFF, WT, bn1_g, bn1_b, bn1_m, bn1_v, B);
    pool_kernel<<<1024, 256>>>(B, POOL);
    se_kernel<<<4, 256>>>(POOL, se1_w1, se1_w2, SCALE);
    scale_kernel<<<16384, 256>>>((float4*)B, SCALE);

    // ---- stage 2 ----
    to_nhwc<<<dim3(512, 8, 4), 256>>>(B, C);
    transpose_dcnw<<<6400, 256>>>(dcn_w2, WT);
    transpose_offw<<<2500, 256>>>(off_w2, OWT);
    offconv_kernel<<<dim3(64, 4, 4), 256>>>(B, OWT, off_b2, OFF);
    deform4_kernel<<<dim3(256, 4), 256, DEF_SMEM>>>(C, OFF, WT, bn2_g, bn2_b, bn2_m, bn2_v, A);
    pool_kernel<<<1024, 256>>>(A, POOL);
    se_kernel<<<4, 256>>>(POOL, se2_w1, se2_w2, SCALE);
    scale_kernel<<<16384, 256>>>((float4*)A, SCALE);

    // ---- final ----
    transpose_redw<<<128, 256>>>(red_w, RT);
    final_kernel<<<dim3(256, 4), 256>>>(A, RT, bn3_g, bn3_b, bn3_m, bn3_v, (float*)d_out);
}